// round 9
// baseline (speedup 1.0000x reference)
#include <cuda_runtime.h>
#include <cstdint>

// MazeBrain: recurrent adaptive-LIF, T=1200, B=16, N=1024.
// One CTA per batch. 512 threads: 2-way row-split float4 gather (16 warps,
// LDG.128, ~17 rows each), one smem partial, 256 owner threads update.
// Dual-parity monotonic spike rings (byte offsets), 2 barriers/step.

#define T_STEPS 1200
#define BATCH   16
#define NN      1024
#define WHIST   1000
#define TPB     512

__global__ void __launch_bounds__(TPB, 1)
mazebrain_kernel(const float* __restrict__ Iext,   // [T,B,N]
                 const float* __restrict__ W,      // [N,N]
                 float* __restrict__ out)          // [2,T,B,N]: spikes, potentials
{
    const int b    = blockIdx.x;
    const int tid  = threadIdx.x;
    const int lane = tid & 31;
    const int rg   = tid >> 8;       // row half: 0 or 1
    const int cg   = tid & 255;      // column group (4 cols)
    const int m0   = cg * 4;
    const bool owner = (rg == 0);

    __shared__ int    s_list[2][NN]; // per-parity spike ring: entries j*4096 (byte offsets)
    __shared__ int    s_cnt[2];      // per-parity monotonic counters
    __shared__ float4 s_part[256];   // rg=1 partials

    if (tid == 0) { s_cnt[0] = 0; s_cnt[1] = 0; }
    __syncthreads();

    float v[4], adapt[4], thr[4], rsum[4];
    int   refr[4];
#pragma unroll
    for (int k = 0; k < 4; k++) {
        v[k] = -65.0f; adapt[k] = 0.0f; thr[k] = -55.0f; rsum[k] = 0.0f; refr[k] = 0;
    }
    int consumed[2] = {0, 0};

    float* __restrict__ spikes_out = out;
    float* __restrict__ pot_out    = out + (size_t)T_STEPS * BATCH * NN;
    const size_t stride = (size_t)BATCH * NN;
    const char* __restrict__ Wb = (const char*)(W + m0);

    size_t ob = (size_t)b * NN + m0;
    float4 Ie_next = owner ? __ldg((const float4*)(Iext + ob))
                           : make_float4(0.f, 0.f, 0.f, 0.f);
    float4 hist_next = make_float4(0.f, 0.f, 0.f, 0.f);

    for (int t = 0; t < T_STEPS; t++) {
        const int p = t & 1;         // append parity
        const int q = p ^ 1;         // consume parity
        const float4 Ie   = Ie_next;
        const float4 hist = hist_next;

        // ---- 2-way row-split sparse gather (entries are byte offsets)
        const int e  = s_cnt[q];
        const int i0 = consumed[q];
        const int nT = e - i0;
        consumed[q] = e;
        const int* __restrict__ lst = s_list[q];

        const int cnt0 = (nT + 1) >> 1;          // rg0 takes the ceil half
        int i = i0 + (rg ? cnt0 : 0);
        int n = rg ? (nT - cnt0) : cnt0;

        float a0 = 0.f, a1 = 0.f, a2 = 0.f, a3 = 0.f;
        while (n >= 16) {
            int o[16];
#pragma unroll
            for (int k = 0; k < 16; k++) o[k] = lst[(i + k) & (NN - 1)];
            float4 r[16];
#pragma unroll
            for (int k = 0; k < 16; k++) r[k] = *(const float4*)(Wb + o[k]);
#pragma unroll
            for (int k = 0; k < 16; k++) {
                a0 += r[k].x; a1 += r[k].y; a2 += r[k].z; a3 += r[k].w;
            }
            i += 16; n -= 16;
        }
        if (n >= 8) {
            int o[8];
#pragma unroll
            for (int k = 0; k < 8; k++) o[k] = lst[(i + k) & (NN - 1)];
            float4 r[8];
#pragma unroll
            for (int k = 0; k < 8; k++) r[k] = *(const float4*)(Wb + o[k]);
#pragma unroll
            for (int k = 0; k < 8; k++) {
                a0 += r[k].x; a1 += r[k].y; a2 += r[k].z; a3 += r[k].w;
            }
            i += 8; n -= 8;
        }
        if (n >= 4) {
            int o[4];
#pragma unroll
            for (int k = 0; k < 4; k++) o[k] = lst[(i + k) & (NN - 1)];
            float4 r[4];
#pragma unroll
            for (int k = 0; k < 4; k++) r[k] = *(const float4*)(Wb + o[k]);
#pragma unroll
            for (int k = 0; k < 4; k++) {
                a0 += r[k].x; a1 += r[k].y; a2 += r[k].z; a3 += r[k].w;
            }
            i += 4; n -= 4;
        }
        while (n > 0) {
            float4 r = *(const float4*)(Wb + lst[i & (NN - 1)]);
            a0 += r.x; a1 += r.y; a2 += r.z; a3 += r.w;
            i++; n--;
        }

        if (!owner) s_part[cg] = make_float4(a0, a1, a2, a3);

        __syncthreads();   // barrier A: partials visible

        if (owner) {
            // ---- reduce partner partial + Iext (fixed order)
            const float4 pp = s_part[cg];
            float Iin[4];
            Iin[0] = Ie.x + (a0 + pp.x);
            Iin[1] = Ie.y + (a1 + pp.y);
            Iin[2] = Ie.z + (a2 + pp.z);
            Iin[3] = Ie.w + (a3 + pp.w);

            // ---- neuron update (integrate -> fire/reset -> adapt -> homeo)
            float spk[4], vout[4];
            bool  fired[4];
#pragma unroll
            for (int k = 0; k < 4; k++) {
                bool  active = (refr[k] <= 0);
                float v_int  = 0.9f * (v[k] + 65.0f) - 65.0f + Iin[k] - adapt[k];
                float v1     = active ? v_int : v[k];
                int   r1     = active ? refr[k] : (refr[k] - 1);
                fired[k] = (v1 >= thr[k]);
                spk[k]  = fired[k] ? 1.0f : 0.0f;
                v[k]    = fired[k] ? -70.0f : v1;
                vout[k] = v[k];
                adapt[k] = (fired[k] ? (adapt[k] + 0.2f) : adapt[k]) * 0.95f;
                refr[k]  = fired[k] ? 5 : r1;
            }

            // ---- warp-aggregated append (1 atomic per warp, byte offsets)
            uint32_t b0 = __ballot_sync(0xffffffffu, fired[0]);
            uint32_t b1 = __ballot_sync(0xffffffffu, fired[1]);
            uint32_t b2 = __ballot_sync(0xffffffffu, fired[2]);
            uint32_t b3 = __ballot_sync(0xffffffffu, fired[3]);
            const int c0 = __popc(b0), c1 = __popc(b1), c2 = __popc(b2), c3 = __popc(b3);
            const int wtot = c0 + c1 + c2 + c3;
            if (wtot) {
                int base = 0;
                if (lane == 0) base = atomicAdd(&s_cnt[p], wtot);
                base = __shfl_sync(0xffffffffu, base, 0);
                const uint32_t lt = (1u << lane) - 1u;
                if (fired[0]) s_list[p][(base + __popc(b0 & lt)) & (NN - 1)] = m0 << 12;
                if (fired[1]) s_list[p][(base + c0 + __popc(b1 & lt)) & (NN - 1)] = (m0 + 1) << 12;
                if (fired[2]) s_list[p][(base + c0 + c1 + __popc(b2 & lt)) & (NN - 1)] = (m0 + 2) << 12;
                if (fired[3]) s_list[p][(base + c0 + c1 + c2 + __popc(b3 & lt)) & (NN - 1)] = (m0 + 3) << 12;
            }

            // ---- outputs (spikes region doubles as the homeostatic history)
            *(float4*)(spikes_out + ob) = make_float4(spk[0], spk[1], spk[2], spk[3]);
            *(float4*)(pot_out    + ob) = make_float4(vout[0], vout[1], vout[2], vout[3]);

            // ---- homeostatic sliding-window rate
            rsum[0] += spk[0] - hist.x; rsum[1] += spk[1] - hist.y;
            rsum[2] += spk[2] - hist.z; rsum[3] += spk[3] - hist.w;
            if (t + 1 >= WHIST) {
#pragma unroll
                for (int k = 0; k < 4; k++) {
                    float ta = thr[k] + 0.001f * (rsum[k] * (1.0f / WHIST) - 0.01f);
                    thr[k] = fminf(fmaxf(ta, 0.1f), 5.0f);
                }
            }

            // ---- prefetch next step's inputs
            const size_t ob_next = ob + stride;
            if (t + 1 < T_STEPS) {
                Ie_next = __ldg((const float4*)(Iext + ob_next));
                hist_next = (t + 1 >= WHIST)
                          ? *(const float4*)(spikes_out + (ob_next - (size_t)WHIST * stride))
                          : make_float4(0.f, 0.f, 0.f, 0.f);
            }
        }
        ob += stride;

        __syncthreads();   // barrier B: append(t) visible before gather(t+1)
    }
}

extern "C" void kernel_launch(void* const* d_in, const int* in_sizes, int n_in,
                              void* d_out, int out_size)
{
    const float* input_current = (const float*)d_in[0];  // [T,B,N]
    const float* W_rec         = (const float*)d_in[1];  // [N,N]
    float* out                 = (float*)d_out;          // [2,T,B,N]
    (void)in_sizes; (void)n_in; (void)out_size;

    mazebrain_kernel<<<BATCH, TPB>>>(input_current, W_rec, out);
}

// round 10
// speedup vs baseline: 1.1178x; 1.1178x over previous
#include <cuda_runtime.h>
#include <cstdint>

// MazeBrain: recurrent adaptive-LIF, T=1200, B=16, N=1024.
// One CTA per batch, 512 threads x 2 cols, dual-parity monotonic spike rings
// (byte offsets), ONE barrier per step. Software-pipelined: first gather batch
// issues right after the barrier; previous step's outputs/homeostasis/prefetch
// execute inside that load shadow.

#define T_STEPS 1200
#define BATCH   16
#define NN      1024
#define WHIST   1000
#define TPB     512     // thread owns neurons 2*tid, 2*tid+1

__global__ void __launch_bounds__(TPB, 1)
mazebrain_kernel(const float* __restrict__ Iext,   // [T,B,N]
                 const float* __restrict__ W,      // [N,N]
                 float* __restrict__ out)          // [2,T,B,N]: spikes, potentials
{
    const int b   = blockIdx.x;
    const int tid = threadIdx.x;
    const int m0  = tid * 2;

    __shared__ int s_list[2][NN];   // per-parity ring: entries are j*4096 (byte offsets)
    __shared__ int s_cnt[2];        // per-parity monotonic counters

    if (tid == 0) { s_cnt[0] = 0; s_cnt[1] = 0; }

    float v0 = -65.f, v1 = -65.f, ad0 = 0.f, ad1 = 0.f;
    float th0 = -55.f, th1 = -55.f, rs0 = 0.f, rs1 = 0.f;
    int   rf0 = 0, rf1 = 0;
    int   consumed[2] = {0, 0};

    float* __restrict__ spikes_out = out;
    float* __restrict__ pot_out    = out + (size_t)T_STEPS * BATCH * NN;
    const size_t stride = (size_t)BATCH * NN;
    const char* __restrict__ Wb = (const char*)(W + m0);

    size_t ob = (size_t)b * NN + m0;
    float2 IeCur   = __ldg((const float2*)(Iext + ob));
    float2 IeNext  = make_float2(0.f, 0.f);
    float2 histNxt = make_float2(0.f, 0.f);

    // deferred previous-step outputs
    float2 pspk = make_float2(0.f, 0.f), pv = make_float2(0.f, 0.f);
    float2 phist = make_float2(0.f, 0.f);
    size_t ob_prev = 0;

    __syncthreads();

    for (int t = 0; t < T_STEPS; t++) {
        const int p = t & 1;        // append parity
        const int q = p ^ 1;        // consume parity

        // ---- counters/list of step t-1 are visible (loop-bottom barrier)
        const int e = s_cnt[q];
        int i = consumed[q];
        int n = e - i;
        consumed[q] = e;
        const int* __restrict__ lst = s_list[q];

        // ---- issue first gather batch (loads go in flight NOW)
        float2 r1[16];
        int n1 = 0;
        if (n >= 16) {
            int o[16];
#pragma unroll
            for (int k = 0; k < 16; k++) o[k] = lst[(i + k) & (NN - 1)];
#pragma unroll
            for (int k = 0; k < 16; k++) r1[k] = *(const float2*)(Wb + o[k]);
            n1 = 16; i += 16; n -= 16;
        } else if (n >= 8) {
            int o[8];
#pragma unroll
            for (int k = 0; k < 8; k++) o[k] = lst[(i + k) & (NN - 1)];
#pragma unroll
            for (int k = 0; k < 8; k++) r1[k] = *(const float2*)(Wb + o[k]);
            n1 = 8; i += 8; n -= 8;
        } else if (n >= 4) {
            int o[4];
#pragma unroll
            for (int k = 0; k < 4; k++) o[k] = lst[(i + k) & (NN - 1)];
#pragma unroll
            for (int k = 0; k < 4; k++) r1[k] = *(const float2*)(Wb + o[k]);
            n1 = 4; i += 4; n -= 4;
        }

        // ---- SHADOW: previous step's deferred work runs under the loads
        if (t) {
            *(float2*)(spikes_out + ob_prev) = pspk;
            *(float2*)(pot_out    + ob_prev) = pv;
            rs0 += pspk.x - phist.x;
            rs1 += pspk.y - phist.y;
            if (t >= WHIST) {
                th0 = fminf(fmaxf(th0 + 0.001f * (rs0 * (1.0f / WHIST) - 0.01f), 0.1f), 5.0f);
                th1 = fminf(fmaxf(th1 + 0.001f * (rs1 * (1.0f / WHIST) - 0.01f), 0.1f), 5.0f);
            }
        }
        if (t + 1 < T_STEPS)
            IeNext = __ldg((const float2*)(Iext + ob + stride));
        histNxt = (t >= WHIST)
                ? *(const float2*)(spikes_out + (ob - (size_t)WHIST * stride))
                : make_float2(0.f, 0.f);

        // ---- rest of the gather
        float a0 = IeCur.x, a1 = IeCur.y;
        while (n >= 16) {
            int o[16];
#pragma unroll
            for (int k = 0; k < 16; k++) o[k] = lst[(i + k) & (NN - 1)];
            float2 r[16];
#pragma unroll
            for (int k = 0; k < 16; k++) r[k] = *(const float2*)(Wb + o[k]);
#pragma unroll
            for (int k = 0; k < 16; k++) { a0 += r[k].x; a1 += r[k].y; }
            i += 16; n -= 16;
        }
        if (n >= 8) {
            int o[8];
#pragma unroll
            for (int k = 0; k < 8; k++) o[k] = lst[(i + k) & (NN - 1)];
            float2 r[8];
#pragma unroll
            for (int k = 0; k < 8; k++) r[k] = *(const float2*)(Wb + o[k]);
#pragma unroll
            for (int k = 0; k < 8; k++) { a0 += r[k].x; a1 += r[k].y; }
            i += 8; n -= 8;
        }
        if (n >= 4) {
            int o[4];
#pragma unroll
            for (int k = 0; k < 4; k++) o[k] = lst[(i + k) & (NN - 1)];
            float2 r[4];
#pragma unroll
            for (int k = 0; k < 4; k++) r[k] = *(const float2*)(Wb + o[k]);
#pragma unroll
            for (int k = 0; k < 4; k++) { a0 += r[k].x; a1 += r[k].y; }
            i += 4; n -= 4;
        }
        while (n > 0) {
            float2 r = *(const float2*)(Wb + lst[i & (NN - 1)]);
            a0 += r.x; a1 += r.y;
            i++; n--;
        }
        // consume the pipelined first batch
        if (n1 == 16) {
#pragma unroll
            for (int k = 0; k < 16; k++) { a0 += r1[k].x; a1 += r1[k].y; }
        } else if (n1 == 8) {
#pragma unroll
            for (int k = 0; k < 8; k++) { a0 += r1[k].x; a1 += r1[k].y; }
        } else if (n1 == 4) {
#pragma unroll
            for (int k = 0; k < 4; k++) { a0 += r1[k].x; a1 += r1[k].y; }
        }

        // ---- neuron update (integrate -> fire/reset -> adapt; homeo deferred)
        bool  act0 = (rf0 <= 0), act1 = (rf1 <= 0);
        float vi0  = 0.9f * (v0 + 65.0f) - 65.0f + a0 - ad0;
        float vi1  = 0.9f * (v1 + 65.0f) - 65.0f + a1 - ad1;
        float v10  = act0 ? vi0 : v0;
        float v11  = act1 ? vi1 : v1;
        int   r10  = act0 ? rf0 : (rf0 - 1);
        int   r11  = act1 ? rf1 : (rf1 - 1);
        bool  f0   = (v10 >= th0);
        bool  f1   = (v11 >= th1);
        float sp0  = f0 ? 1.0f : 0.0f;
        float sp1  = f1 ? 1.0f : 0.0f;
        v0 = f0 ? -70.0f : v10;
        v1 = f1 ? -70.0f : v11;
        ad0 = (f0 ? (ad0 + 0.2f) : ad0) * 0.95f;
        ad1 = (f1 ? (ad1 + 0.2f) : ad1) * 0.95f;
        rf0 = f0 ? 5 : r10;
        rf1 = f1 ? 5 : r11;

        // ---- distributed append (byte offsets j*4096)
        if (f0) {
            int idx = atomicAdd(&s_cnt[p], 1);
            s_list[p][idx & (NN - 1)] = m0 << 12;
        }
        if (f1) {
            int idx = atomicAdd(&s_cnt[p], 1);
            s_list[p][idx & (NN - 1)] = (m0 + 1) << 12;
        }

        // ---- defer outputs/homeo to next iteration's load shadow
        pspk    = make_float2(sp0, sp1);
        pv      = make_float2(v0, v1);
        phist   = histNxt;
        ob_prev = ob;
        IeCur   = IeNext;
        ob     += stride;

        __syncthreads();   // orders append(t) before gather(t+1)
    }

    // epilogue: final step's outputs
    *(float2*)(spikes_out + ob_prev) = pspk;
    *(float2*)(pot_out    + ob_prev) = pv;
}

extern "C" void kernel_launch(void* const* d_in, const int* in_sizes, int n_in,
                              void* d_out, int out_size)
{
    const float* input_current = (const float*)d_in[0];  // [T,B,N]
    const float* W_rec         = (const float*)d_in[1];  // [N,N]
    float* out                 = (float*)d_out;          // [2,T,B,N]
    (void)in_sizes; (void)n_in; (void)out_size;

    mazebrain_kernel<<<BATCH, TPB>>>(input_current, W_rec, out);
}